// round 15
// baseline (speedup 1.0000x reference)
#include <cuda_runtime.h>
#include <math.h>
#include <stdint.h>

typedef unsigned long long ull;

// output layout (float32)
#define OFF_CTC_S 0
#define OFF_LEN_S 328320
#define OFF_CTC_C 328352
#define OFF_LEN_C 656672
#define OFF_CLOSE 656704

// ---------------- scratch (device globals; no allocation) ----------------
__device__ float g_xz[2u*32u*1024u*1024u];      // xz for lstm0; reused (smaller) for lstm1
__device__ float g_pool[2*32*342*256];          // pooled lstm0 output
__device__ float g_hA[2*32*342*256];            // lstm1 pass A output
__device__ float g_hB[2*32*342*256];            // lstm1 pass B output

// ---------------- cluster / mbarrier helpers ----------------
__device__ __forceinline__ uint32_t smem_u32(const void* p) {
    uint32_t a;
    asm("{ .reg .u64 t; cvta.to.shared.u64 t, %1; cvt.u32.u64 %0, t; }" : "=r"(a) : "l"(p));
    return a;
}
__device__ __forceinline__ uint32_t mapa_rank(uint32_t addr, uint32_t rank) {
    uint32_t r;
    asm("mapa.shared::cluster.u32 %0, %1, %2;" : "=r"(r) : "r"(addr), "r"(rank));
    return r;
}
__device__ __forceinline__ void mbar_init(uint32_t addr, uint32_t count) {
    asm volatile("mbarrier.init.shared.b64 [%0], %1;" :: "r"(addr), "r"(count) : "memory");
}
__device__ __forceinline__ void mbar_expect(uint32_t addr, uint32_t tx) {
    asm volatile("mbarrier.arrive.expect_tx.shared.b64 _, [%0], %1;" :: "r"(addr), "r"(tx) : "memory");
}
// CTA-scope acquire wait: the complete_tx mechanism orders the async data
// delivery against barrier completion (same semantics as TMA); consumer only
// needs cta-scope acquire for its local SMEM reads. This is the pattern used
// by the reference ptx_helpers MBARRIER_WAIT_PARITY.
__device__ __forceinline__ void mbar_wait(uint32_t addr, uint32_t parity) {
    asm volatile(
        "{\n\t.reg .pred P;\n"
        "LW_%=:\n\t"
        "mbarrier.try_wait.parity.acquire.cta.shared::cta.b64 P, [%0], %1, 0x989680;\n\t"
        "@P bra LD_%=;\n\t"
        "bra LW_%=;\n"
        "LD_%=:\n\t}"
        :: "r"(addr), "r"(parity) : "memory");
}
__device__ __forceinline__ void st_async_b64(uint32_t raddr, ull v, uint32_t rmbar) {
    asm volatile("st.async.shared::cluster.mbarrier::complete_tx::bytes.b64 [%0], %1, [%2];"
                 :: "r"(raddr), "l"(v), "r"(rmbar) : "memory");
}

// fast sigmoid / tanh (EX2 + RCP based; ~1e-6 rel err)
__device__ __forceinline__ float fsigm(float x) {
    return __fdividef(1.f, 1.f + __expf(-x));
}
__device__ __forceinline__ float ftanh_(float x) {
    return __fdividef(2.f, 1.f + __expf(-2.f * x)) - 1.f;
}

__device__ __forceinline__ void fma_bc(float4& a, float hs, const float4 w) {
    a.x = fmaf(hs, w.x, a.x);
    a.y = fmaf(hs, w.y, a.y);
    a.z = fmaf(hs, w.z, a.z);
    a.w = fmaf(hs, w.w, a.w);
}

// ---------------- tiled GEMM with bias (mode 0: xz0 = clip(x) @ Wk0 + b) ----------------
__global__ __launch_bounds__(256) void gemm_bias_kernel(
    const float* __restrict__ Aext,
    const float* __restrict__ W0, const float* __restrict__ W1,
    const float* __restrict__ b0, const float* __restrict__ b1,
    int M, int K)
{
    const int branch = blockIdx.z;
    const float* W = branch ? W1 : W0;
    const float* bias = branch ? b1 : b0;
    const float* A = Aext;
    float* out = g_xz + (size_t)branch * (32u*1024u*1024u);

    __shared__ float As[64][17];
    __shared__ float Bs[16][128];

    const int tid = threadIdx.x;
    const int tr = tid >> 5;
    const int tc = tid & 31;
    const int m0 = blockIdx.y * 64;
    const int n0 = blockIdx.x * 128;

    float acc[8][4];
    #pragma unroll
    for (int i = 0; i < 8; i++)
        #pragma unroll
        for (int j = 0; j < 4; j++) acc[i][j] = 0.f;

    for (int k0 = 0; k0 < K; k0 += 16) {
        #pragma unroll
        for (int i = tid; i < 1024; i += 256) {
            int m = i >> 4, k = i & 15;
            float v = 0.f;
            if (k0 + k < K) {
                v = A[(size_t)(m0 + m) * K + k0 + k];
                v = fminf(3.f, fmaxf(-3.f, v));
            }
            As[m][k] = v;
        }
        #pragma unroll
        for (int i = tid; i < 2048; i += 256) {
            int k = i >> 7, n = i & 127;
            Bs[k][n] = (k0 + k < K) ? W[(size_t)(k0 + k) * 1024 + n0 + n] : 0.f;
        }
        __syncthreads();
        #pragma unroll
        for (int k = 0; k < 16; k++) {
            float4 bv = *(const float4*)&Bs[k][tc * 4];
            #pragma unroll
            for (int i = 0; i < 8; i++) {
                float a = As[tr * 8 + i][k];
                acc[i][0] += a * bv.x;
                acc[i][1] += a * bv.y;
                acc[i][2] += a * bv.z;
                acc[i][3] += a * bv.w;
            }
        }
        __syncthreads();
    }
    float4 bv = *(const float4*)&bias[n0 + tc * 4];
    #pragma unroll
    for (int i = 0; i < 8; i++) {
        float4 r = make_float4(acc[i][0] + bv.x, acc[i][1] + bv.y,
                               acc[i][2] + bv.z, acc[i][3] + bv.w);
        *(float4*)&out[(size_t)(m0 + tr * 8 + i) * 1024 + n0 + tc * 4] = r;
    }
}

// ---------------- 128x128 tiled GEMM with bias (modes 1/2: lstm1 inputs) ----------------
__global__ __launch_bounds__(256) void gemm_bias128_kernel(
    const float* __restrict__ W0, const float* __restrict__ W1,
    const float* __restrict__ b0, const float* __restrict__ b1,
    int mode)
{
    const int branch = blockIdx.z;
    const float* W = branch ? W1 : W0;
    const float* bias = branch ? b1 : b0;
    const float* A = ((mode == 1) ? g_pool : g_hA) + (size_t)branch * (32*342*256);
    float* out = g_xz + (size_t)branch * (32u*342u*1024u);

    __shared__ float As[128][24];   // [m][k], padded
    __shared__ float Bs[16][132];   // [k][n], padded

    const int tid = threadIdx.x;
    const int ty = tid >> 4;
    const int tx = tid & 15;
    const int m0 = blockIdx.y * 128;
    const int n0 = blockIdx.x * 128;

    float acc[8][8];
    #pragma unroll
    for (int i = 0; i < 8; i++)
        #pragma unroll
        for (int j = 0; j < 8; j++) acc[i][j] = 0.f;

    for (int k0 = 0; k0 < 256; k0 += 16) {
        #pragma unroll
        for (int s = tid; s < 512; s += 256) {
            int m = s >> 2, kq = s & 3;
            float4 v = make_float4(0.f, 0.f, 0.f, 0.f);
            if (m0 + m < 10944)
                v = *(const float4*)&A[(size_t)(m0 + m) * 256 + k0 + kq * 4];
            *(float4*)&As[m][kq * 4] = v;
        }
        #pragma unroll
        for (int s = tid; s < 512; s += 256) {
            int k = s >> 5, nq = s & 31;
            *(float4*)&Bs[k][nq * 4] = *(const float4*)&W[(size_t)(k0 + k) * 1024 + n0 + nq * 4];
        }
        __syncthreads();
        #pragma unroll
        for (int k = 0; k < 16; k++) {
            float4 bb0 = *(const float4*)&Bs[k][tx * 4];
            float4 bb1 = *(const float4*)&Bs[k][64 + tx * 4];
            #pragma unroll
            for (int i = 0; i < 8; i++) {
                float a = As[ty * 8 + i][k];
                acc[i][0] = fmaf(a, bb0.x, acc[i][0]);
                acc[i][1] = fmaf(a, bb0.y, acc[i][1]);
                acc[i][2] = fmaf(a, bb0.z, acc[i][2]);
                acc[i][3] = fmaf(a, bb0.w, acc[i][3]);
                acc[i][4] = fmaf(a, bb1.x, acc[i][4]);
                acc[i][5] = fmaf(a, bb1.y, acc[i][5]);
                acc[i][6] = fmaf(a, bb1.z, acc[i][6]);
                acc[i][7] = fmaf(a, bb1.w, acc[i][7]);
            }
        }
        __syncthreads();
    }
    float4 bv0 = *(const float4*)&bias[n0 + tx * 4];
    float4 bv1 = *(const float4*)&bias[n0 + 64 + tx * 4];
    #pragma unroll
    for (int i = 0; i < 8; i++) {
        int m = m0 + ty * 8 + i;
        if (m < 10944) {
            float4 r0 = make_float4(acc[i][0] + bv0.x, acc[i][1] + bv0.y,
                                    acc[i][2] + bv0.z, acc[i][3] + bv0.w);
            float4 r1 = make_float4(acc[i][4] + bv1.x, acc[i][5] + bv1.y,
                                    acc[i][6] + bv1.z, acc[i][7] + bv1.w);
            *(float4*)&out[(size_t)m * 1024 + n0 + tx * 4] = r0;
            *(float4*)&out[(size_t)m * 1024 + n0 + 64 + tx * 4] = r1;
        }
    }
}

// ---------------- persistent recurrent LSTM kernel (8-CTA cluster gangs) ----------------
// Per-source mbarriers (16 = 2 parities x 8 sources); warp kg waits ONLY on
// barrier (par, kg). Waits are CTA-scope acquire (complete_tx orders the data).
// ps is double-buffered by parity: warp kg's rewrite of ps[par] at t+2 is
// ordered (via the barrier causality chain through all gate warps' sends)
// after all gates(t) reads of ps[par].
__global__ void __launch_bounds__(256, 1) __cluster_dims__(8, 1, 1)
lstm_rec_kernel(
    const float* __restrict__ Wr0, const float* __restrict__ Wr1,
    const int* __restrict__ x_len, int T, int mode)
{
    const int blk = blockIdx.x;
    const int gang = blk >> 3;
    const int cg = blk & 7;
    const int branch = gang >> 3;
    const int bg = gang & 7;
    const int j0 = cg * 32;
    const float* Wr = branch ? Wr1 : Wr0;

    const int tid = threadIdx.x;
    const int kg = tid >> 5;          // warp = k-group 0..7 == source CTA of its slice
    const int lane = tid & 31;
    const int kbase = kg * 32;

    __shared__ __align__(16) float h_s[2][4][256];      // double-buffered h (8KB)
    __shared__ __align__(16) float ps[2][8][4][128];    // parity-buffered partials (32KB)
    __shared__ __align__(8) ull mbar_s[16];

    // ---- mbarrier init + initial expects (idx = par*8 + src) ----
    const uint32_t mbb = smem_u32(&mbar_s[0]);
    if (tid == 0) {
        #pragma unroll
        for (int i = 0; i < 16; i++) mbar_init(mbb + i * 8, 1);
    }
    __syncthreads();
    if (tid == 0) {
        #pragma unroll
        for (int i = 0; i < 16; i++) mbar_expect(mbb + i * 8, 512);
    }

    // ---- zero h(0) buffer ----
    {
        float* p = &h_s[0][0][0];
        #pragma unroll
        for (int i = tid; i < 1024; i += 256) p[i] = 0.f;
    }

    // ---- load weight slice into registers (once): 32 k x 4 cols ----
    float4 wreg[32];
    {
        const int c0 = lane * 4;
        const int gate = c0 >> 5;
        const int jj = c0 & 31;
        const float* wb = Wr + gate * 256 + j0 + jj;
        #pragma unroll
        for (int kk = 0; kk < 32; kk++) {
            const float* wr = wb + (size_t)(kbase + kk) * 1024;
            wreg[kk] = make_float4(wr[0], wr[1], wr[2], wr[3]);
        }
    }

    // ---- gate role (tid < 128): gb = tid>>5, gjj = tid&31 ----
    const int gb = tid >> 5;
    const int gjj = tid & 31;
    const float NEGINF = __int_as_float(0xff800000);
    float cst = 0.f;
    float poolm = NEGINF;
    int mylen = 0;
    const int Tstride = (mode == 0) ? 1024 : 342;
    const float* xzg = nullptr;
    float *poolp = nullptr, *hop = nullptr;
    if (tid < 128) {
        const int b_glob = bg * 4 + gb;
        int xl = x_len[b_glob];
        mylen = (mode == 0) ? xl : (xl + 2) / 3;
        xzg = g_xz + (size_t)branch * 32u * (size_t)Tstride * 1024u
            + (size_t)b_glob * Tstride * 1024u + j0 + gjj;
        poolp = g_pool + ((size_t)(branch * 32 + b_glob) * 342) * 256 + j0 + gjj;
        hop = ((mode == 1) ? g_hA : g_hB) + ((size_t)(branch * 32 + b_glob) * 342) * 256 + j0 + gjj;
    }

    // peer base addresses (8 ranks)
    uint32_t peer_h[8], peer_mb[8];
    {
        const uint32_t hb = smem_u32(&h_s[0][0][0]);
        #pragma unroll
        for (int r = 0; r < 8; r++) {
            peer_h[r] = mapa_rank(hb, r);
            peer_mb[r] = mapa_rank(mbb, r);
        }
    }

    __syncthreads();
    // cluster sync: mbarriers + expects visible before any peer st.async
    asm volatile("barrier.cluster.arrive.aligned;" ::: "memory");
    asm volatile("barrier.cluster.wait.aligned;" ::: "memory");

    uint32_t phase0 = 0, phase1 = 0;     // per-warp parity for its own source barrier

    for (int t = 0; t < T; t++) {
        const int par = t & 1;
        const int par1 = par ^ 1;

        // prefetch xz for this step (gate threads; independent of h)
        float x0, x1, x2, x3;
        if (tid < 128) {
            const float* p = xzg + (size_t)t * 1024;
            x0 = p[0]; x1 = p[256]; x2 = p[512]; x3 = p[768];
        }

        // ---- per-source wait: warp kg waits ONLY for slice kg, then re-arms ----
        if (t > 0) {
            const uint32_t mb = mbb + (uint32_t)((par * 8 + kg) << 3);
            if (par) { mbar_wait(mb, phase1); phase1 ^= 1; }
            else     { mbar_wait(mb, phase0); phase0 ^= 1; }
            if (lane == 0) mbar_expect(mb, 512);
        }

        // ---- GEMM: partial z over owned 32 k rows (slice kg), 4 cols, 4 batches ----
        #pragma unroll
        for (int b = 0; b < 4; b++) {
            float4 acc = make_float4(0.f, 0.f, 0.f, 0.f);
            #pragma unroll
            for (int kk4 = 0; kk4 < 8; kk4++) {
                float4 h4 = *(const float4*)&h_s[par][b][kbase + 4 * kk4];
                fma_bc(acc, h4.x, wreg[4 * kk4 + 0]);
                fma_bc(acc, h4.y, wreg[4 * kk4 + 1]);
                fma_bc(acc, h4.z, wreg[4 * kk4 + 2]);
                fma_bc(acc, h4.w, wreg[4 * kk4 + 3]);
            }
            *(float4*)&ps[par][kg][b][4 * lane] = acc;
        }
        __syncthreads();

        // ---- gates: fused 8-way reduce + math + packed publish (gate warps) ----
        if (tid < 128) {
            float zi = x0, zf = x1, zg = x2, zo = x3;
            #pragma unroll
            for (int q = 0; q < 8; q++) {
                const float* pp = &ps[par][q][gb][0];
                zi += pp[gjj];
                zf += pp[32 + gjj];
                zg += pp[64 + gjj];
                zo += pp[96 + gjj];
            }
            float iv = fsigm(zi), fv = fsigm(zf), gv = ftanh_(zg), ov = fsigm(zo);
            float cn = fv * cst + iv * gv;
            float hn = ov * ftanh_(cn);
            bool m = (t < mylen);
            float hp = h_s[par][gb][j0 + gjj];
            float hv = m ? hn : hp;
            cst = m ? cn : cst;

            // pair-pack and send h(t+1) to all 8 cluster CTAs (even lanes, b64)
            // target barrier at each peer: (par1, src = cg)
            float hv_hi = __shfl_down_sync(0xffffffffu, hv, 1);
            if (t + 1 < T && (gjj & 1) == 0) {
                ull hd;
                asm("mov.b64 %0, {%1, %2};" : "=l"(hd) : "f"(hv), "f"(hv_hi));
                const uint32_t off = (uint32_t)(((par1 * 4 + gb) << 8) + j0 + gjj) * 4u;
                const uint32_t moff = (uint32_t)((par1 * 8 + cg) << 3);
                #pragma unroll
                for (int r = 0; r < 8; r++)
                    st_async_b64(peer_h[r] + off, hd, peer_mb[r] + moff);
            }

            // outputs (after sends — off the signal path)
            if (mode == 0) {
                poolm = fmaxf(poolm, hv);
                if ((t % 3) == 1) {
                    poolp[(size_t)(t / 3) * 256] = poolm;
                    poolm = NEGINF;
                }
            } else {
                hop[(size_t)t * 256] = hv;
            }
        }
    }

    // flush final pool window (covers t = 1022,1023)
    if (mode == 0 && tid < 128) {
        poolp[341u * 256] = poolm;
    }
}

// ---------------- CTC projection: out = hB @ ctc_w + ctc_b ----------------
__global__ __launch_bounds__(256) void ctc_kernel(
    const float* __restrict__ W, const float* __restrict__ bias, float* __restrict__ out)
{
    __shared__ float As[8][256];
    const int r0 = blockIdx.x * 8;
    for (int i = threadIdx.x; i < 2048; i += 256) {
        As[i >> 8][i & 255] = g_hB[(size_t)r0 * 256 + i];
    }
    __syncthreads();
    if (threadIdx.x < 240) {
        const int rl = threadIdx.x / 30;
        const int n = threadIdx.x % 30;
        float acc = bias[n];
        #pragma unroll 8
        for (int k = 0; k < 256; k++) acc += As[rl][k] * __ldg(&W[k * 30 + n]);
        const int r = r0 + rl;
        const int branch = r / 10944;
        const int idx = r - branch * 10944;
        const size_t o = (branch ? (size_t)OFF_CTC_C : (size_t)OFF_CTC_S) + (size_t)idx * 30 + n;
        out[o] = acc;
    }
}

// ---------------- lens + close ----------------
__global__ void finalize_kernel(const int* __restrict__ x_len, float* __restrict__ out)
{
    const int b = blockIdx.x;
    const float* s = out + OFF_CTC_S + (size_t)b * 10260;
    const float* c = out + OFF_CTC_C + (size_t)b * 10260;
    int ok = 1;
    for (int i = threadIdx.x; i < 10260; i += 256) {
        if (!(fabsf(s[i] - c[i]) < 1e-5f)) ok = 0;
    }
    int allok = __syncthreads_and(ok);
    if (threadIdx.x == 0) {
        float len = (float)((x_len[b] + 2) / 3);
        out[OFF_LEN_S + b] = len;
        out[OFF_LEN_C + b] = len;
        out[OFF_CLOSE + b] = allok ? 1.f : 0.f;
    }
}

// ---------------- launch ----------------
extern "C" void kernel_launch(void* const* d_in, const int* in_sizes, int n_in,
                              void* d_out, int out_size)
{
    const float* x      = (const float*)d_in[0];
    const int*   x_len  = (const int*)  d_in[1];
    const float* ws0_k  = (const float*)d_in[2];
    const float* ws0_r  = (const float*)d_in[3];
    const float* ws0_b  = (const float*)d_in[4];
    const float* ws1_k  = (const float*)d_in[5];
    const float* ws1_r  = (const float*)d_in[6];
    const float* ws1_b  = (const float*)d_in[7];
    const float* wc0_k  = (const float*)d_in[8];
    const float* wc0_r  = (const float*)d_in[9];
    const float* wc0_b  = (const float*)d_in[10];
    const float* wc1_k  = (const float*)d_in[11];
    const float* wc1_r  = (const float*)d_in[12];
    const float* wc1_b  = (const float*)d_in[13];
    const float* ctc_w  = (const float*)d_in[14];
    const float* ctc_b  = (const float*)d_in[15];
    float* out = (float*)d_out;

    // xz0 = clip(x) @ Wk0 + b0   (M = 32*1024, K = 40)
    gemm_bias_kernel<<<dim3(8, 512, 2), 256>>>(x, ws0_k, wc0_k, ws0_b, wc0_b, 32768, 40);

    // lstm0 + fused maxpool3
    lstm_rec_kernel<<<128, 256>>>(ws0_r, wc0_r, x_len, 1024, 0);

    // xz1A = pooled @ Wk1 + b1   (M = 32*342, K = 256)
    gemm_bias128_kernel<<<dim3(8, 86, 2), 256>>>(ws1_k, wc1_k, ws1_b, wc1_b, 1);

    // lstm1 pass A
    lstm_rec_kernel<<<128, 256>>>(ws1_r, wc1_r, x_len, 342, 1);

    // xz1B = hA @ Wk1 + b1
    gemm_bias128_kernel<<<dim3(8, 86, 2), 256>>>(ws1_k, wc1_k, ws1_b, wc1_b, 2);

    // lstm1 pass B
    lstm_rec_kernel<<<128, 256>>>(ws1_r, wc1_r, x_len, 342, 2);

    // CTC projection for both branches
    ctc_kernel<<<2736, 256>>>(ctc_w, ctc_b, out);

    // lens + close
    finalize_kernel<<<32, 256>>>(x_len, out);
}

// round 16
// speedup vs baseline: 1.0174x; 1.0174x over previous
#include <cuda_runtime.h>
#include <math.h>
#include <stdint.h>

typedef unsigned long long ull;

// output layout (float32)
#define OFF_CTC_S 0
#define OFF_LEN_S 328320
#define OFF_CTC_C 328352
#define OFF_LEN_C 656672
#define OFF_CLOSE 656704

// ---------------- scratch (device globals; no allocation) ----------------
__device__ float g_xz[2u*32u*1024u*1024u];      // xz for lstm0; reused (smaller) for lstm1
__device__ float g_pool[2*32*342*256];          // pooled lstm0 output
__device__ float g_hA[2*32*342*256];            // lstm1 pass A output
__device__ float g_hB[2*32*342*256];            // lstm1 pass B output

// ---------------- cluster / mbarrier helpers ----------------
__device__ __forceinline__ uint32_t smem_u32(const void* p) {
    uint32_t a;
    asm("{ .reg .u64 t; cvta.to.shared.u64 t, %1; cvt.u32.u64 %0, t; }" : "=r"(a) : "l"(p));
    return a;
}
__device__ __forceinline__ uint32_t mapa_rank(uint32_t addr, uint32_t rank) {
    uint32_t r;
    asm("mapa.shared::cluster.u32 %0, %1, %2;" : "=r"(r) : "r"(addr), "r"(rank));
    return r;
}
__device__ __forceinline__ void mbar_init(uint32_t addr, uint32_t count) {
    asm volatile("mbarrier.init.shared.b64 [%0], %1;" :: "r"(addr), "r"(count) : "memory");
}
__device__ __forceinline__ void mbar_expect(uint32_t addr, uint32_t tx) {
    asm volatile("mbarrier.arrive.expect_tx.shared.b64 _, [%0], %1;" :: "r"(addr), "r"(tx) : "memory");
}
__device__ __forceinline__ void mbar_wait(uint32_t addr, uint32_t parity) {
    asm volatile(
        "{\n\t.reg .pred P;\n"
        "LW_%=:\n\t"
        "mbarrier.try_wait.parity.acquire.cluster.shared::cta.b64 P, [%0], %1, 0x989680;\n\t"
        "@P bra LD_%=;\n\t"
        "bra LW_%=;\n"
        "LD_%=:\n\t}"
        :: "r"(addr), "r"(parity) : "memory");
}
__device__ __forceinline__ void st_async_b64(uint32_t raddr, ull v, uint32_t rmbar) {
    asm volatile("st.async.shared::cluster.mbarrier::complete_tx::bytes.b64 [%0], %1, [%2];"
                 :: "r"(raddr), "l"(v), "r"(rmbar) : "memory");
}
// cp.async 16B with zero-fill when pred==0 (src not dereferenced if size 0)
__device__ __forceinline__ void cp_async16(uint32_t dst, const void* src, int pred) {
    asm volatile("cp.async.ca.shared.global [%0], [%1], 16, %2;"
                 :: "r"(dst), "l"(src), "r"(pred ? 16 : 0) : "memory");
}
__device__ __forceinline__ void cp_commit() {
    asm volatile("cp.async.commit_group;" ::: "memory");
}
__device__ __forceinline__ void cp_wait1() {
    asm volatile("cp.async.wait_group 1;" ::: "memory");
}

// fast sigmoid / tanh (EX2 + RCP based; ~1e-6 rel err)
__device__ __forceinline__ float fsigm(float x) {
    return __fdividef(1.f, 1.f + __expf(-x));
}
__device__ __forceinline__ float ftanh_(float x) {
    return __fdividef(2.f, 1.f + __expf(-2.f * x)) - 1.f;
}

__device__ __forceinline__ void fma_bc(float4& a, float hs, const float4 w) {
    a.x = fmaf(hs, w.x, a.x);
    a.y = fmaf(hs, w.y, a.y);
    a.z = fmaf(hs, w.z, a.z);
    a.w = fmaf(hs, w.w, a.w);
}

// ---------------- tiled GEMM with bias (mode 0: xz0 = clip(x) @ Wk0 + b) ----------------
__global__ __launch_bounds__(256) void gemm_bias_kernel(
    const float* __restrict__ Aext,
    const float* __restrict__ W0, const float* __restrict__ W1,
    const float* __restrict__ b0, const float* __restrict__ b1,
    int M, int K)
{
    const int branch = blockIdx.z;
    const float* W = branch ? W1 : W0;
    const float* bias = branch ? b1 : b0;
    const float* A = Aext;
    float* out = g_xz + (size_t)branch * (32u*1024u*1024u);

    __shared__ float As[64][17];
    __shared__ float Bs[16][128];

    const int tid = threadIdx.x;
    const int tr = tid >> 5;
    const int tc = tid & 31;
    const int m0 = blockIdx.y * 64;
    const int n0 = blockIdx.x * 128;

    float acc[8][4];
    #pragma unroll
    for (int i = 0; i < 8; i++)
        #pragma unroll
        for (int j = 0; j < 4; j++) acc[i][j] = 0.f;

    for (int k0 = 0; k0 < K; k0 += 16) {
        #pragma unroll
        for (int i = tid; i < 1024; i += 256) {
            int m = i >> 4, k = i & 15;
            float v = 0.f;
            if (k0 + k < K) {
                v = A[(size_t)(m0 + m) * K + k0 + k];
                v = fminf(3.f, fmaxf(-3.f, v));
            }
            As[m][k] = v;
        }
        #pragma unroll
        for (int i = tid; i < 2048; i += 256) {
            int k = i >> 7, n = i & 127;
            Bs[k][n] = (k0 + k < K) ? W[(size_t)(k0 + k) * 1024 + n0 + n] : 0.f;
        }
        __syncthreads();
        #pragma unroll
        for (int k = 0; k < 16; k++) {
            float4 bv = *(const float4*)&Bs[k][tc * 4];
            #pragma unroll
            for (int i = 0; i < 8; i++) {
                float a = As[tr * 8 + i][k];
                acc[i][0] += a * bv.x;
                acc[i][1] += a * bv.y;
                acc[i][2] += a * bv.z;
                acc[i][3] += a * bv.w;
            }
        }
        __syncthreads();
    }
    float4 bv = *(const float4*)&bias[n0 + tc * 4];
    #pragma unroll
    for (int i = 0; i < 8; i++) {
        float4 r = make_float4(acc[i][0] + bv.x, acc[i][1] + bv.y,
                               acc[i][2] + bv.z, acc[i][3] + bv.w);
        *(float4*)&out[(size_t)(m0 + tr * 8 + i) * 1024 + n0 + tc * 4] = r;
    }
}

// ---------------- 128x128 tiled GEMM, cp.async 2-stage pipeline (modes 1/2) ----------------
// out[10944,1024] = A[10944,256] @ W[256,1024] + b.  8x8 microtile per thread.
// Identical FMA order to the round-13 kernel (bit-identical results); the only
// change is double-buffered cp.async staging of the 16-wide k-tiles.
__global__ __launch_bounds__(256) void gemm_bias128_kernel(
    const float* __restrict__ W0, const float* __restrict__ W1,
    const float* __restrict__ b0, const float* __restrict__ b1,
    int mode)
{
    const int branch = blockIdx.z;
    const float* W = branch ? W1 : W0;
    const float* bias = branch ? b1 : b0;
    const float* A = ((mode == 1) ? g_pool : g_hA) + (size_t)branch * (32*342*256);
    float* out = g_xz + (size_t)branch * (32u*342u*1024u);

    __shared__ float As[2][128][20];    // [buf][m][k] pad 20 (80B rows, 16B aligned)
    __shared__ float Bs[2][16][132];    // [buf][k][n] pad 132 (528B rows, 16B aligned)

    const int tid = threadIdx.x;
    const int ty = tid >> 4;
    const int tx = tid & 15;
    const int m0 = blockIdx.y * 128;
    const int n0 = blockIdx.x * 128;

    // per-thread cp.async slots (2 As float4 + 2 Bs float4 per stage)
    const int a_m0 = tid >> 2, a_kq = tid & 3;          // slots tid, tid+256
    const int b_k0 = tid >> 5, b_nq = tid & 31;

    float acc[8][8];
    #pragma unroll
    for (int i = 0; i < 8; i++)
        #pragma unroll
        for (int j = 0; j < 8; j++) acc[i][j] = 0.f;

    // ---- stage issue: 128x16 A tile + 16x128 B tile into buffer buf ----
    auto issue_stage = [&](int buf, int k0) {
        // As slots: s = tid and s = tid+256  (m = s>>2, kq = s&3)
        {
            int m = a_m0, kq = a_kq;
            cp_async16(smem_u32(&As[buf][m][kq * 4]),
                       &A[(size_t)(m0 + m) * 256 + k0 + kq * 4], (m0 + m) < 10944);
            m = a_m0 + 64;
            cp_async16(smem_u32(&As[buf][m][kq * 4]),
                       &A[(size_t)(m0 + m) * 256 + k0 + kq * 4], (m0 + m) < 10944);
        }
        // Bs slots: s = tid and s = tid+256  (k = s>>5, nq = s&31)
        {
            int k = b_k0, nq = b_nq;
            cp_async16(smem_u32(&Bs[buf][k][nq * 4]),
                       &W[(size_t)(k0 + k) * 1024 + n0 + nq * 4], 1);
            k = b_k0 + 8;
            cp_async16(smem_u32(&Bs[buf][k][nq * 4]),
                       &W[(size_t)(k0 + k) * 1024 + n0 + nq * 4], 1);
        }
    };

    issue_stage(0, 0);
    cp_commit();

    #pragma unroll 1
    for (int kt = 0; kt < 16; kt++) {
        if (kt + 1 < 16) issue_stage((kt + 1) & 1, (kt + 1) * 16);
        cp_commit();                 // always commit (empty group on last iter)
        cp_wait1();                  // stage kt resident
        __syncthreads();

        const int buf = kt & 1;
        #pragma unroll
        for (int k = 0; k < 16; k++) {
            float4 bb0 = *(const float4*)&Bs[buf][k][tx * 4];
            float4 bb1 = *(const float4*)&Bs[buf][k][64 + tx * 4];
            #pragma unroll
            for (int i = 0; i < 8; i++) {
                float a = As[buf][ty * 8 + i][k];
                acc[i][0] = fmaf(a, bb0.x, acc[i][0]);
                acc[i][1] = fmaf(a, bb0.y, acc[i][1]);
                acc[i][2] = fmaf(a, bb0.z, acc[i][2]);
                acc[i][3] = fmaf(a, bb0.w, acc[i][3]);
                acc[i][4] = fmaf(a, bb1.x, acc[i][4]);
                acc[i][5] = fmaf(a, bb1.y, acc[i][5]);
                acc[i][6] = fmaf(a, bb1.z, acc[i][6]);
                acc[i][7] = fmaf(a, bb1.w, acc[i][7]);
            }
        }
        __syncthreads();             // protect buffer before stage kt+2 overwrites
    }

    float4 bv0 = *(const float4*)&bias[n0 + tx * 4];
    float4 bv1 = *(const float4*)&bias[n0 + 64 + tx * 4];
    #pragma unroll
    for (int i = 0; i < 8; i++) {
        int m = m0 + ty * 8 + i;
        if (m < 10944) {
            float4 r0 = make_float4(acc[i][0] + bv0.x, acc[i][1] + bv0.y,
                                    acc[i][2] + bv0.z, acc[i][3] + bv0.w);
            float4 r1 = make_float4(acc[i][4] + bv1.x, acc[i][5] + bv1.y,
                                    acc[i][6] + bv1.z, acc[i][7] + bv1.w);
            *(float4*)&out[(size_t)m * 1024 + n0 + tx * 4] = r0;
            *(float4*)&out[(size_t)m * 1024 + n0 + 64 + tx * 4] = r1;
        }
    }
}

// ---------------- persistent recurrent LSTM kernel (8-CTA cluster gangs) ----------------
// EXACT round-14 kernel (best measured). Per-source mbarriers: 16 = 2 parities
// x 8 source CTAs. Warp kg waits ONLY on barrier (par, kg) — the slice its
// GEMM needs. expect_tx per barrier = 4 batches * 32 units * 4B = 512 B.
__global__ void __launch_bounds__(256, 1) __cluster_dims__(8, 1, 1)
lstm_rec_kernel(
    const float* __restrict__ Wr0, const float* __restrict__ Wr1,
    const int* __restrict__ x_len, int T, int mode)
{
    const int blk = blockIdx.x;
    const int gang = blk >> 3;
    const int cg = blk & 7;
    const int branch = gang >> 3;
    const int bg = gang & 7;
    const int j0 = cg * 32;
    const float* Wr = branch ? Wr1 : Wr0;

    const int tid = threadIdx.x;
    const int kg = tid >> 5;          // warp = k-group 0..7 == source CTA of its slice
    const int lane = tid & 31;
    const int kbase = kg * 32;

    __shared__ __align__(16) float h_s[2][4][256];    // double-buffered h (8KB)
    __shared__ __align__(16) float ps[8][4][128];     // partial sums (16KB)
    __shared__ __align__(8) ull mbar_s[16];

    // ---- mbarrier init + initial expects (idx = par*8 + src) ----
    const uint32_t mbb = smem_u32(&mbar_s[0]);
    if (tid == 0) {
        #pragma unroll
        for (int i = 0; i < 16; i++) mbar_init(mbb + i * 8, 1);
    }
    __syncthreads();
    if (tid == 0) {
        #pragma unroll
        for (int i = 0; i < 16; i++) mbar_expect(mbb + i * 8, 512);
    }

    // ---- zero h(0) buffer ----
    {
        float* p = &h_s[0][0][0];
        #pragma unroll
        for (int i = tid; i < 1024; i += 256) p[i] = 0.f;
    }

    // ---- load weight slice into registers (once): 32 k x 4 cols ----
    float4 wreg[32];
    {
        const int c0 = lane * 4;
        const int gate = c0 >> 5;
        const int jj = c0 & 31;
        const float* wb = Wr + gate * 256 + j0 + jj;
        #pragma unroll
        for (int kk = 0; kk < 32; kk++) {
            const float* wr = wb + (size_t)(kbase + kk) * 1024;
            wreg[kk] = make_float4(wr[0], wr[1], wr[2], wr[3]);
        }
    }

    // ---- gate role (tid < 128): gb = tid>>5, gjj = tid&31 ----
    const int gb = tid >> 5;
    const int gjj = tid & 31;
    const float NEGINF = __int_as_float(0xff800000);
    float cst = 0.f;
    float poolm = NEGINF;
    int mylen = 0;
    const int Tstride = (mode == 0) ? 1024 : 342;
    const float* xzg = nullptr;
    float *poolp = nullptr, *hop = nullptr;
    if (tid < 128) {
        const int b_glob = bg * 4 + gb;
        int xl = x_len[b_glob];
        mylen = (mode == 0) ? xl : (xl + 2) / 3;
        xzg = g_xz + (size_t)branch * 32u * (size_t)Tstride * 1024u
            + (size_t)b_glob * Tstride * 1024u + j0 + gjj;
        poolp = g_pool + ((size_t)(branch * 32 + b_glob) * 342) * 256 + j0 + gjj;
        hop = ((mode == 1) ? g_hA : g_hB) + ((size_t)(branch * 32 + b_glob) * 342) * 256 + j0 + gjj;
    }

    // peer base addresses (8 ranks)
    uint32_t peer_h[8], peer_mb[8];
    {
        const uint32_t hb = smem_u32(&h_s[0][0][0]);
        #pragma unroll
        for (int r = 0; r < 8; r++) {
            peer_h[r] = mapa_rank(hb, r);
            peer_mb[r] = mapa_rank(mbb, r);
        }
    }

    __syncthreads();
    // cluster sync: mbarriers + expects visible before any peer st.async
    asm volatile("barrier.cluster.arrive.aligned;" ::: "memory");
    asm volatile("barrier.cluster.wait.aligned;" ::: "memory");

    uint32_t phase0 = 0, phase1 = 0;     // per-warp parity for its own source barrier

    for (int t = 0; t < T; t++) {
        const int par = t & 1;
        const int par1 = par ^ 1;

        // prefetch xz for this step (gate threads; independent of h)
        float x0, x1, x2, x3;
        if (tid < 128) {
            const float* p = xzg + (size_t)t * 1024;
            x0 = p[0]; x1 = p[256]; x2 = p[512]; x3 = p[768];
        }

        // ---- per-source wait: warp kg waits ONLY for slice kg, then re-arms ----
        if (t > 0) {
            const uint32_t mb = mbb + (uint32_t)((par * 8 + kg) << 3);
            if (par) { mbar_wait(mb, phase1); phase1 ^= 1; }
            else     { mbar_wait(mb, phase0); phase0 ^= 1; }
            if (lane == 0) mbar_expect(mb, 512);
        }

        // ---- GEMM: partial z over owned 32 k rows (slice kg), 4 cols, 4 batches ----
        #pragma unroll
        for (int b = 0; b < 4; b++) {
            float4 acc = make_float4(0.f, 0.f, 0.f, 0.f);
            #pragma unroll
            for (int kk4 = 0; kk4 < 8; kk4++) {
                float4 h4 = *(const float4*)&h_s[par][b][kbase + 4 * kk4];
                fma_bc(acc, h4.x, wreg[4 * kk4 + 0]);
                fma_bc(acc, h4.y, wreg[4 * kk4 + 1]);
                fma_bc(acc, h4.z, wreg[4 * kk4 + 2]);
                fma_bc(acc, h4.w, wreg[4 * kk4 + 3]);
            }
            *(float4*)&ps[kg][b][4 * lane] = acc;
        }
        __syncthreads();

        // ---- gates: fused 8-way reduce + math + packed publish (gate warps) ----
        if (tid < 128) {
            float zi = x0, zf = x1, zg = x2, zo = x3;
            #pragma unroll
            for (int q = 0; q < 8; q++) {
                const float* pp = &ps[q][gb][0];
                zi += pp[gjj];
                zf += pp[32 + gjj];
                zg += pp[64 + gjj];
                zo += pp[96 + gjj];
            }
            float iv = fsigm(zi), fv = fsigm(zf), gv = ftanh_(zg), ov = fsigm(zo);
            float cn = fv * cst + iv * gv;
            float hn = ov * ftanh_(cn);
            bool m = (t < mylen);
            float hp = h_s[par][gb][j0 + gjj];
            float hv = m ? hn : hp;
            cst = m ? cn : cst;

            // pair-pack and send h(t+1) to all 8 cluster CTAs (even lanes, b64)
            // target barrier at each peer: (par1, src = cg)
            float hv_hi = __shfl_down_sync(0xffffffffu, hv, 1);
            if (t + 1 < T && (gjj & 1) == 0) {
                ull hd;
                asm("mov.b64 %0, {%1, %2};" : "=l"(hd) : "f"(hv), "f"(hv_hi));
                const uint32_t off = (uint32_t)(((par1 * 4 + gb) << 8) + j0 + gjj) * 4u;
                const uint32_t moff = (uint32_t)((par1 * 8 + cg) << 3);
                #pragma unroll
                for (int r = 0; r < 8; r++)
                    st_async_b64(peer_h[r] + off, hd, peer_mb[r] + moff);
            }

            // outputs (after sends — off the signal path)
            if (mode == 0) {
                poolm = fmaxf(poolm, hv);
                if ((t % 3) == 1) {
                    poolp[(size_t)(t / 3) * 256] = poolm;
                    poolm = NEGINF;
                }
            } else {
                hop[(size_t)t * 256] = hv;
            }
        }
    }

    // flush final pool window (covers t = 1022,1023)
    if (mode == 0 && tid < 128) {
        poolp[341u * 256] = poolm;
    }
}

// ---------------- CTC projection: out = hB @ ctc_w + ctc_b ----------------
__global__ __launch_bounds__(256) void ctc_kernel(
    const float* __restrict__ W, const float* __restrict__ bias, float* __restrict__ out)
{
    __shared__ float As[8][256];
    const int r0 = blockIdx.x * 8;
    for (int i = threadIdx.x; i < 2048; i += 256) {
        As[i >> 8][i & 255] = g_hB[(size_t)r0 * 256 + i];
    }
    __syncthreads();
    if (threadIdx.x < 240) {
        const int rl = threadIdx.x / 30;
        const int n = threadIdx.x % 30;
        float acc = bias[n];
        #pragma unroll 8
        for (int k = 0; k < 256; k++) acc += As[rl][k] * __ldg(&W[k * 30 + n]);
        const int r = r0 + rl;
        const int branch = r / 10944;
        const int idx = r - branch * 10944;
        const size_t o = (branch ? (size_t)OFF_CTC_C : (size_t)OFF_CTC_S) + (size_t)idx * 30 + n;
        out[o] = acc;
    }
}

// ---------------- lens + close ----------------
__global__ void finalize_kernel(const int* __restrict__ x_len, float* __restrict__ out)
{
    const int b = blockIdx.x;
    const float* s = out + OFF_CTC_S + (size_t)b * 10260;
    const float* c = out + OFF_CTC_C + (size_t)b * 10260;
    int ok = 1;
    for (int i = threadIdx.x; i < 10260; i += 256) {
        if (!(fabsf(s[i] - c[i]) < 1e-5f)) ok = 0;
    }
    int allok = __syncthreads_and(ok);
    if (threadIdx.x == 0) {
        float len = (float)((x_len[b] + 2) / 3);
        out[OFF_LEN_S + b] = len;
        out[OFF_LEN_C + b] = len;
        out[OFF_CLOSE + b] = allok ? 1.f : 0.f;
    }
}

// ---------------- launch ----------------
extern "C" void kernel_launch(void* const* d_in, const int* in_sizes, int n_in,
                              void* d_out, int out_size)
{
    const float* x      = (const float*)d_in[0];
    const int*   x_len  = (const int*)  d_in[1];
    const float* ws0_k  = (const float*)d_in[2];
    const float* ws0_r  = (const float*)d_in[3];
    const float* ws0_b  = (const float*)d_in[4];
    const float* ws1_k  = (const float*)d_in[5];
    const float* ws1_r  = (const float*)d_in[6];
    const float* ws1_b  = (const float*)d_in[7];
    const float* wc0_k  = (const float*)d_in[8];
    const float* wc0_r  = (const float*)d_in[9];
    const float* wc0_b  = (const float*)d_in[10];
    const float* wc1_k  = (const float*)d_in[11];
    const float* wc1_r  = (const float*)d_in[12];
    const float* wc1_b  = (const float*)d_in[13];
    const float* ctc_w  = (const float*)d_in[14];
    const float* ctc_b  = (const float*)d_in[15];
    float* out = (float*)d_out;

    // xz0 = clip(x) @ Wk0 + b0   (M = 32*1024, K = 40)
    gemm_bias_kernel<<<dim3(8, 512, 2), 256>>>(x, ws0_k, wc0_k, ws0_b, wc0_b, 32768, 40);

    // lstm0 + fused maxpool3
    lstm_rec_kernel<<<128, 256>>>(ws0_r, wc0_r, x_len, 1024, 0);

    // xz1A = pooled @ Wk1 + b1   (M = 32*342, K = 256)
    gemm_bias128_kernel<<<dim3(8, 86, 2), 256>>>(ws1_k, wc1_k, ws1_b, wc1_b, 1);

    // lstm1 pass A
    lstm_rec_kernel<<<128, 256>>>(ws1_r, wc1_r, x_len, 342, 1);

    // xz1B = hA @ Wk1 + b1
    gemm_bias128_kernel<<<dim3(8, 86, 2), 256>>>(ws1_k, wc1_k, ws1_b, wc1_b, 2);

    // lstm1 pass B
    lstm_rec_kernel<<<128, 256>>>(ws1_r, wc1_r, x_len, 342, 2);

    // CTC projection for both branches
    ctc_kernel<<<2736, 256>>>(ctc_w, ctc_b, out);

    // lens + close
    finalize_kernel<<<32, 256>>>(x_len, out);
}

// round 17
// speedup vs baseline: 1.0301x; 1.0125x over previous
#include <cuda_runtime.h>
#include <math.h>
#include <stdint.h>

typedef unsigned long long ull;

// output layout (float32)
#define OFF_CTC_S 0
#define OFF_LEN_S 328320
#define OFF_CTC_C 328352
#define OFF_LEN_C 656672
#define OFF_CLOSE 656704

// ---------------- scratch (device globals; no allocation) ----------------
__device__ float g_xz[2u*32u*1024u*1024u];      // xz for lstm0; reused (smaller) for lstm1
__device__ float g_pool[2*32*342*256];          // pooled lstm0 output
__device__ float g_hA[2*32*342*256];            // lstm1 pass A output
__device__ float g_hB[2*32*342*256];            // lstm1 pass B output

// ---------------- cluster / mbarrier helpers ----------------
__device__ __forceinline__ uint32_t smem_u32(const void* p) {
    uint32_t a;
    asm("{ .reg .u64 t; cvta.to.shared.u64 t, %1; cvt.u32.u64 %0, t; }" : "=r"(a) : "l"(p));
    return a;
}
__device__ __forceinline__ uint32_t mapa_rank(uint32_t addr, uint32_t rank) {
    uint32_t r;
    asm("mapa.shared::cluster.u32 %0, %1, %2;" : "=r"(r) : "r"(addr), "r"(rank));
    return r;
}
__device__ __forceinline__ void mbar_init(uint32_t addr, uint32_t count) {
    asm volatile("mbarrier.init.shared.b64 [%0], %1;" :: "r"(addr), "r"(count) : "memory");
}
__device__ __forceinline__ void mbar_expect(uint32_t addr, uint32_t tx) {
    asm volatile("mbarrier.arrive.expect_tx.shared.b64 _, [%0], %1;" :: "r"(addr), "r"(tx) : "memory");
}
__device__ __forceinline__ void mbar_wait(uint32_t addr, uint32_t parity) {
    asm volatile(
        "{\n\t.reg .pred P;\n"
        "LW_%=:\n\t"
        "mbarrier.try_wait.parity.acquire.cluster.shared::cta.b64 P, [%0], %1, 0x989680;\n\t"
        "@P bra LD_%=;\n\t"
        "bra LW_%=;\n"
        "LD_%=:\n\t}"
        :: "r"(addr), "r"(parity) : "memory");
}
__device__ __forceinline__ void st_async_b64(uint32_t raddr, ull v, uint32_t rmbar) {
    asm volatile("st.async.shared::cluster.mbarrier::complete_tx::bytes.b64 [%0], %1, [%2];"
                 :: "r"(raddr), "l"(v), "r"(rmbar) : "memory");
}
// cp.async 16B with zero-fill when pred==0 (src not dereferenced if size 0)
__device__ __forceinline__ void cp_async16(uint32_t dst, const void* src, int pred) {
    asm volatile("cp.async.ca.shared.global [%0], [%1], 16, %2;"
                 :: "r"(dst), "l"(src), "r"(pred ? 16 : 0) : "memory");
}
__device__ __forceinline__ void cp_commit() {
    asm volatile("cp.async.commit_group;" ::: "memory");
}
__device__ __forceinline__ void cp_wait1() {
    asm volatile("cp.async.wait_group 1;" ::: "memory");
}

// fast sigmoid / tanh (EX2 + RCP based; ~1e-6 rel err)
__device__ __forceinline__ float fsigm(float x) {
    return __fdividef(1.f, 1.f + __expf(-x));
}
__device__ __forceinline__ float ftanh_(float x) {
    return __fdividef(2.f, 1.f + __expf(-2.f * x)) - 1.f;
}

__device__ __forceinline__ void fma_bc(float4& a, float hs, const float4 w) {
    a.x = fmaf(hs, w.x, a.x);
    a.y = fmaf(hs, w.y, a.y);
    a.z = fmaf(hs, w.z, a.z);
    a.w = fmaf(hs, w.w, a.w);
}

// ---------------- xz0 GEMM: out[32768,1024] = clip(x)[32768,40] @ Wk0 + b ----------------
// 128x128 tile, K=40 staged whole in SMEM (no k-loop). 8x8 microtile/thread.
// k accumulated sequentially 0..39 -> bit-identical to the previous kernel.
__global__ __launch_bounds__(256) void gemm_bias0_kernel(
    const float* __restrict__ Aext,
    const float* __restrict__ W0, const float* __restrict__ W1,
    const float* __restrict__ b0, const float* __restrict__ b1)
{
    const int branch = blockIdx.z;
    const float* W = branch ? W1 : W0;
    const float* bias = branch ? b1 : b0;
    float* out = g_xz + (size_t)branch * (32u*1024u*1024u);

    __shared__ float As[128][44];   // [m][k], 40 + pad (176B rows, 16B aligned)
    __shared__ float Bs[40][132];   // [k][n], 128 + pad (528B rows, 16B aligned)

    const int tid = threadIdx.x;
    const int ty = tid >> 4;        // 0..15 -> rows ty*8..+7
    const int tx = tid & 15;        // cols tx*4..+3 and 64+tx*4..+3
    const int m0 = blockIdx.y * 128;
    const int n0 = blockIdx.x * 128;

    // load A tile: 128 rows x 40 floats = 1280 float4 (5 per thread), clipped
    #pragma unroll
    for (int s = tid; s < 1280; s += 256) {
        const int m = s / 10, kq = s % 10;
        float4 v = *(const float4*)&Aext[(size_t)(m0 + m) * 40 + kq * 4];
        v.x = fminf(3.f, fmaxf(-3.f, v.x));
        v.y = fminf(3.f, fmaxf(-3.f, v.y));
        v.z = fminf(3.f, fmaxf(-3.f, v.z));
        v.w = fminf(3.f, fmaxf(-3.f, v.w));
        *(float4*)&As[m][kq * 4] = v;
    }
    // load B tile: 40 rows x 128 floats = 1280 float4 (5 per thread)
    #pragma unroll
    for (int s = tid; s < 1280; s += 256) {
        const int k = s >> 5, nq = s & 31;
        *(float4*)&Bs[k][nq * 4] = *(const float4*)&W[(size_t)k * 1024 + n0 + nq * 4];
    }
    __syncthreads();

    float acc[8][8];
    #pragma unroll
    for (int i = 0; i < 8; i++)
        #pragma unroll
        for (int j = 0; j < 8; j++) acc[i][j] = 0.f;

    #pragma unroll 8
    for (int k = 0; k < 40; k++) {
        float4 bb0 = *(const float4*)&Bs[k][tx * 4];
        float4 bb1 = *(const float4*)&Bs[k][64 + tx * 4];
        #pragma unroll
        for (int i = 0; i < 8; i++) {
            float a = As[ty * 8 + i][k];
            acc[i][0] = fmaf(a, bb0.x, acc[i][0]);
            acc[i][1] = fmaf(a, bb0.y, acc[i][1]);
            acc[i][2] = fmaf(a, bb0.z, acc[i][2]);
            acc[i][3] = fmaf(a, bb0.w, acc[i][3]);
            acc[i][4] = fmaf(a, bb1.x, acc[i][4]);
            acc[i][5] = fmaf(a, bb1.y, acc[i][5]);
            acc[i][6] = fmaf(a, bb1.z, acc[i][6]);
            acc[i][7] = fmaf(a, bb1.w, acc[i][7]);
        }
    }

    float4 bv0 = *(const float4*)&bias[n0 + tx * 4];
    float4 bv1 = *(const float4*)&bias[n0 + 64 + tx * 4];
    #pragma unroll
    for (int i = 0; i < 8; i++) {
        const int m = m0 + ty * 8 + i;
        float4 r0 = make_float4(acc[i][0] + bv0.x, acc[i][1] + bv0.y,
                                acc[i][2] + bv0.z, acc[i][3] + bv0.w);
        float4 r1 = make_float4(acc[i][4] + bv1.x, acc[i][5] + bv1.y,
                                acc[i][6] + bv1.z, acc[i][7] + bv1.w);
        *(float4*)&out[(size_t)m * 1024 + n0 + tx * 4] = r0;
        *(float4*)&out[(size_t)m * 1024 + n0 + 64 + tx * 4] = r1;
    }
}

// ---------------- 128x128 tiled GEMM, cp.async 2-stage pipeline (modes 1/2) ----------------
__global__ __launch_bounds__(256) void gemm_bias128_kernel(
    const float* __restrict__ W0, const float* __restrict__ W1,
    const float* __restrict__ b0, const float* __restrict__ b1,
    int mode)
{
    const int branch = blockIdx.z;
    const float* W = branch ? W1 : W0;
    const float* bias = branch ? b1 : b0;
    const float* A = ((mode == 1) ? g_pool : g_hA) + (size_t)branch * (32*342*256);
    float* out = g_xz + (size_t)branch * (32u*342u*1024u);

    __shared__ float As[2][128][20];
    __shared__ float Bs[2][16][132];

    const int tid = threadIdx.x;
    const int ty = tid >> 4;
    const int tx = tid & 15;
    const int m0 = blockIdx.y * 128;
    const int n0 = blockIdx.x * 128;

    const int a_m0 = tid >> 2, a_kq = tid & 3;
    const int b_k0 = tid >> 5, b_nq = tid & 31;

    float acc[8][8];
    #pragma unroll
    for (int i = 0; i < 8; i++)
        #pragma unroll
        for (int j = 0; j < 8; j++) acc[i][j] = 0.f;

    auto issue_stage = [&](int buf, int k0) {
        {
            int m = a_m0, kq = a_kq;
            cp_async16(smem_u32(&As[buf][m][kq * 4]),
                       &A[(size_t)(m0 + m) * 256 + k0 + kq * 4], (m0 + m) < 10944);
            m = a_m0 + 64;
            cp_async16(smem_u32(&As[buf][m][kq * 4]),
                       &A[(size_t)(m0 + m) * 256 + k0 + kq * 4], (m0 + m) < 10944);
        }
        {
            int k = b_k0, nq = b_nq;
            cp_async16(smem_u32(&Bs[buf][k][nq * 4]),
                       &W[(size_t)(k0 + k) * 1024 + n0 + nq * 4], 1);
            k = b_k0 + 8;
            cp_async16(smem_u32(&Bs[buf][k][nq * 4]),
                       &W[(size_t)(k0 + k) * 1024 + n0 + nq * 4], 1);
        }
    };

    issue_stage(0, 0);
    cp_commit();

    #pragma unroll 1
    for (int kt = 0; kt < 16; kt++) {
        if (kt + 1 < 16) issue_stage((kt + 1) & 1, (kt + 1) * 16);
        cp_commit();
        cp_wait1();
        __syncthreads();

        const int buf = kt & 1;
        #pragma unroll
        for (int k = 0; k < 16; k++) {
            float4 bb0 = *(const float4*)&Bs[buf][k][tx * 4];
            float4 bb1 = *(const float4*)&Bs[buf][k][64 + tx * 4];
            #pragma unroll
            for (int i = 0; i < 8; i++) {
                float a = As[buf][ty * 8 + i][k];
                acc[i][0] = fmaf(a, bb0.x, acc[i][0]);
                acc[i][1] = fmaf(a, bb0.y, acc[i][1]);
                acc[i][2] = fmaf(a, bb0.z, acc[i][2]);
                acc[i][3] = fmaf(a, bb0.w, acc[i][3]);
                acc[i][4] = fmaf(a, bb1.x, acc[i][4]);
                acc[i][5] = fmaf(a, bb1.y, acc[i][5]);
                acc[i][6] = fmaf(a, bb1.z, acc[i][6]);
                acc[i][7] = fmaf(a, bb1.w, acc[i][7]);
            }
        }
        __syncthreads();
    }

    float4 bv0 = *(const float4*)&bias[n0 + tx * 4];
    float4 bv1 = *(const float4*)&bias[n0 + 64 + tx * 4];
    #pragma unroll
    for (int i = 0; i < 8; i++) {
        int m = m0 + ty * 8 + i;
        if (m < 10944) {
            float4 r0 = make_float4(acc[i][0] + bv0.x, acc[i][1] + bv0.y,
                                    acc[i][2] + bv0.z, acc[i][3] + bv0.w);
            float4 r1 = make_float4(acc[i][4] + bv1.x, acc[i][5] + bv1.y,
                                    acc[i][6] + bv1.z, acc[i][7] + bv1.w);
            *(float4*)&out[(size_t)m * 1024 + n0 + tx * 4] = r0;
            *(float4*)&out[(size_t)m * 1024 + n0 + 64 + tx * 4] = r1;
        }
    }
}

// ---------------- persistent recurrent LSTM kernel (8-CTA cluster gangs) ----------------
// EXACT round-14/16 kernel (best measured). Per-source mbarriers: 16 = 2
// parities x 8 source CTAs. Warp kg waits ONLY on barrier (par, kg).
__global__ void __launch_bounds__(256, 1) __cluster_dims__(8, 1, 1)
lstm_rec_kernel(
    const float* __restrict__ Wr0, const float* __restrict__ Wr1,
    const int* __restrict__ x_len, int T, int mode)
{
    const int blk = blockIdx.x;
    const int gang = blk >> 3;
    const int cg = blk & 7;
    const int branch = gang >> 3;
    const int bg = gang & 7;
    const int j0 = cg * 32;
    const float* Wr = branch ? Wr1 : Wr0;

    const int tid = threadIdx.x;
    const int kg = tid >> 5;
    const int lane = tid & 31;
    const int kbase = kg * 32;

    __shared__ __align__(16) float h_s[2][4][256];
    __shared__ __align__(16) float ps[8][4][128];
    __shared__ __align__(8) ull mbar_s[16];

    const uint32_t mbb = smem_u32(&mbar_s[0]);
    if (tid == 0) {
        #pragma unroll
        for (int i = 0; i < 16; i++) mbar_init(mbb + i * 8, 1);
    }
    __syncthreads();
    if (tid == 0) {
        #pragma unroll
        for (int i = 0; i < 16; i++) mbar_expect(mbb + i * 8, 512);
    }

    {
        float* p = &h_s[0][0][0];
        #pragma unroll
        for (int i = tid; i < 1024; i += 256) p[i] = 0.f;
    }

    float4 wreg[32];
    {
        const int c0 = lane * 4;
        const int gate = c0 >> 5;
        const int jj = c0 & 31;
        const float* wb = Wr + gate * 256 + j0 + jj;
        #pragma unroll
        for (int kk = 0; kk < 32; kk++) {
            const float* wr = wb + (size_t)(kbase + kk) * 1024;
            wreg[kk] = make_float4(wr[0], wr[1], wr[2], wr[3]);
        }
    }

    const int gb = tid >> 5;
    const int gjj = tid & 31;
    const float NEGINF = __int_as_float(0xff800000);
    float cst = 0.f;
    float poolm = NEGINF;
    int mylen = 0;
    const int Tstride = (mode == 0) ? 1024 : 342;
    const float* xzg = nullptr;
    float *poolp = nullptr, *hop = nullptr;
    if (tid < 128) {
        const int b_glob = bg * 4 + gb;
        int xl = x_len[b_glob];
        mylen = (mode == 0) ? xl : (xl + 2) / 3;
        xzg = g_xz + (size_t)branch * 32u * (size_t)Tstride * 1024u
            + (size_t)b_glob * Tstride * 1024u + j0 + gjj;
        poolp = g_pool + ((size_t)(branch * 32 + b_glob) * 342) * 256 + j0 + gjj;
        hop = ((mode == 1) ? g_hA : g_hB) + ((size_t)(branch * 32 + b_glob) * 342) * 256 + j0 + gjj;
    }

    uint32_t peer_h[8], peer_mb[8];
    {
        const uint32_t hb = smem_u32(&h_s[0][0][0]);
        #pragma unroll
        for (int r = 0; r < 8; r++) {
            peer_h[r] = mapa_rank(hb, r);
            peer_mb[r] = mapa_rank(mbb, r);
        }
    }

    __syncthreads();
    asm volatile("barrier.cluster.arrive.aligned;" ::: "memory");
    asm volatile("barrier.cluster.wait.aligned;" ::: "memory");

    uint32_t phase0 = 0, phase1 = 0;

    for (int t = 0; t < T; t++) {
        const int par = t & 1;
        const int par1 = par ^ 1;

        float x0, x1, x2, x3;
        if (tid < 128) {
            const float* p = xzg + (size_t)t * 1024;
            x0 = p[0]; x1 = p[256]; x2 = p[512]; x3 = p[768];
        }

        if (t > 0) {
            const uint32_t mb = mbb + (uint32_t)((par * 8 + kg) << 3);
            if (par) { mbar_wait(mb, phase1); phase1 ^= 1; }
            else     { mbar_wait(mb, phase0); phase0 ^= 1; }
            if (lane == 0) mbar_expect(mb, 512);
        }

        #pragma unroll
        for (int b = 0; b < 4; b++) {
            float4 acc = make_float4(0.f, 0.f, 0.f, 0.f);
            #pragma unroll
            for (int kk4 = 0; kk4 < 8; kk4++) {
                float4 h4 = *(const float4*)&h_s[par][b][kbase + 4 * kk4];
                fma_bc(acc, h4.x, wreg[4 * kk4 + 0]);
                fma_bc(acc, h4.y, wreg[4 * kk4 + 1]);
                fma_bc(acc, h4.z, wreg[4 * kk4 + 2]);
                fma_bc(acc, h4.w, wreg[4 * kk4 + 3]);
            }
            *(float4*)&ps[kg][b][4 * lane] = acc;
        }
        __syncthreads();

        if (tid < 128) {
            float zi = x0, zf = x1, zg = x2, zo = x3;
            #pragma unroll
            for (int q = 0; q < 8; q++) {
                const float* pp = &ps[q][gb][0];
                zi += pp[gjj];
                zf += pp[32 + gjj];
                zg += pp[64 + gjj];
                zo += pp[96 + gjj];
            }
            float iv = fsigm(zi), fv = fsigm(zf), gv = ftanh_(zg), ov = fsigm(zo);
            float cn = fv * cst + iv * gv;
            float hn = ov * ftanh_(cn);
            bool m = (t < mylen);
            float hp = h_s[par][gb][j0 + gjj];
            float hv = m ? hn : hp;
            cst = m ? cn : cst;

            float hv_hi = __shfl_down_sync(0xffffffffu, hv, 1);
            if (t + 1 < T && (gjj & 1) == 0) {
                ull hd;
                asm("mov.b64 %0, {%1, %2};" : "=l"(hd) : "f"(hv), "f"(hv_hi));
                const uint32_t off = (uint32_t)(((par1 * 4 + gb) << 8) + j0 + gjj) * 4u;
                const uint32_t moff = (uint32_t)((par1 * 8 + cg) << 3);
                #pragma unroll
                for (int r = 0; r < 8; r++)
                    st_async_b64(peer_h[r] + off, hd, peer_mb[r] + moff);
            }

            if (mode == 0) {
                poolm = fmaxf(poolm, hv);
                if ((t % 3) == 1) {
                    poolp[(size_t)(t / 3) * 256] = poolm;
                    poolm = NEGINF;
                }
            } else {
                hop[(size_t)t * 256] = hv;
            }
        }
    }

    if (mode == 0 && tid < 128) {
        poolp[341u * 256] = poolm;
    }
}

// ---------------- CTC projection: out = hB @ ctc_w + ctc_b ----------------
// ctc_w (256x30) staged in SMEM once per block.
__global__ __launch_bounds__(256) void ctc_kernel(
    const float* __restrict__ W, const float* __restrict__ bias, float* __restrict__ out)
{
    __shared__ float As[8][256];
    __shared__ float Ws[7680];      // [k][n] 256x30
    const int r0 = blockIdx.x * 8;
    for (int i = threadIdx.x; i < 2048; i += 256) {
        As[i >> 8][i & 255] = g_hB[(size_t)r0 * 256 + i];
    }
    for (int i = threadIdx.x; i < 7680; i += 256) {
        Ws[i] = W[i];
    }
    __syncthreads();
    if (threadIdx.x < 240) {
        const int rl = threadIdx.x / 30;
        const int n = threadIdx.x % 30;
        float acc = bias[n];
        #pragma unroll 8
        for (int k = 0; k < 256; k++) acc += As[rl][k] * Ws[k * 30 + n];
        const int r = r0 + rl;
        const int branch = r / 10944;
        const int idx = r - branch * 10944;
        const size_t o = (branch ? (size_t)OFF_CTC_C : (size_t)OFF_CTC_S) + (size_t)idx * 30 + n;
        out[o] = acc;
    }
}

// ---------------- lens + close ----------------
__global__ void finalize_kernel(const int* __restrict__ x_len, float* __restrict__ out)
{
    const int b = blockIdx.x;
    const float* s = out + OFF_CTC_S + (size_t)b * 10260;
    const float* c = out + OFF_CTC_C + (size_t)b * 10260;
    int ok = 1;
    for (int i = threadIdx.x; i < 10260; i += 256) {
        if (!(fabsf(s[i] - c[i]) < 1e-5f)) ok = 0;
    }
    int allok = __syncthreads_and(ok);
    if (threadIdx.x == 0) {
        float len = (float)((x_len[b] + 2) / 3);
        out[OFF_LEN_S + b] = len;
        out[OFF_LEN_C + b] = len;
        out[OFF_CLOSE + b] = allok ? 1.f : 0.f;
    }
}

// ---------------- launch ----------------
extern "C" void kernel_launch(void* const* d_in, const int* in_sizes, int n_in,
                              void* d_out, int out_size)
{
    const float* x      = (const float*)d_in[0];
    const int*   x_len  = (const int*)  d_in[1];
    const float* ws0_k  = (const float*)d_in[2];
    const float* ws0_r  = (const float*)d_in[3];
    const float* ws0_b  = (const float*)d_in[4];
    const float* ws1_k  = (const float*)d_in[5];
    const float* ws1_r  = (const float*)d_in[6];
    const float* ws1_b  = (const float*)d_in[7];
    const float* wc0_k  = (const float*)d_in[8];
    const float* wc0_r  = (const float*)d_in[9];
    const float* wc0_b  = (const float*)d_in[10];
    const float* wc1_k  = (const float*)d_in[11];
    const float* wc1_r  = (const float*)d_in[12];
    const float* wc1_b  = (const float*)d_in[13];
    const float* ctc_w  = (const float*)d_in[14];
    const float* ctc_b  = (const float*)d_in[15];
    float* out = (float*)d_out;

    // xz0 = clip(x) @ Wk0 + b0   (M = 32*1024, K = 40) — 128x128 single-pass tile
    gemm_bias0_kernel<<<dim3(8, 256, 2), 256>>>(x, ws0_k, wc0_k, ws0_b, wc0_b);

    // lstm0 + fused maxpool3
    lstm_rec_kernel<<<128, 256>>>(ws0_r, wc0_r, x_len, 1024, 0);

    // xz1A = pooled @ Wk1 + b1   (M = 32*342, K = 256)
    gemm_bias128_kernel<<<dim3(8, 86, 2), 256>>>(ws1_k, wc1_k, ws1_b, wc1_b, 1);

    // lstm1 pass A
    lstm_rec_kernel<<<128, 256>>>(ws1_r, wc1_r, x_len, 342, 1);

    // xz1B = hA @ Wk1 + b1
    gemm_bias128_kernel<<<dim3(8, 86, 2), 256>>>(ws1_k, wc1_k, ws1_b, wc1_b, 2);

    // lstm1 pass B
    lstm_rec_kernel<<<128, 256>>>(ws1_r, wc1_r, x_len, 342, 2);

    // CTC projection for both branches
    ctc_kernel<<<2736, 256>>>(ctc_w, ctc_b, out);

    // lens + close
    finalize_kernel<<<32, 256>>>(x_len, out);
}